// round 10
// baseline (speedup 1.0000x reference)
#include <cuda_runtime.h>
#include <cuda_bf16.h>
#include <cstdint>

#define NI 128
#define NC 128
#define RR 36
#define WW 32
#define DD 1024
#define MROWS (NI*RR)   // 4608
#define NCOLS (NC*WW)   // 4096

// Scratch (allocation-free contract: __device__ globals)
__device__ float g_sim[(size_t)NC * NI * RR * WW];   // [c][i][r][w]
__device__ float g_gimg[(size_t)NI * RR * RR];
__device__ float g_gcap[(size_t)NC * WW * WW];
__device__ __nv_bfloat16 g_ahi[(size_t)MROWS * DD];
__device__ __nv_bfloat16 g_alo[(size_t)MROWS * DD];
__device__ __nv_bfloat16 g_bhi[(size_t)NCOLS * DD];
__device__ __nv_bfloat16 g_blo[(size_t)NCOLS * DD];

// ---------------- helpers ----------------
__device__ __forceinline__ uint32_t smem_u32(const void* p) {
    uint32_t a;
    asm("{ .reg .u64 t; cvta.to.shared.u64 t, %1; cvt.u32.u64 %0, t; }" : "=r"(a) : "l"(p));
    return a;
}
__device__ __forceinline__ uint32_t swz128(uint32_t off) { return off ^ ((off >> 3) & 0x70); }

__device__ __forceinline__ void ldsm_x4(uint32_t* r, uint32_t addr) {
    asm volatile("ldmatrix.sync.aligned.m8n8.x4.shared.b16 {%0,%1,%2,%3}, [%4];"
                 : "=r"(r[0]), "=r"(r[1]), "=r"(r[2]), "=r"(r[3]) : "r"(addr));
}
__device__ __forceinline__ void mma16816(float* d, const uint32_t* a, const uint32_t* b) {
    asm volatile(
        "mma.sync.aligned.m16n8k16.row.col.f32.bf16.bf16.f32 "
        "{%0,%1,%2,%3}, {%4,%5,%6,%7}, {%8,%9}, {%0,%1,%2,%3};"
        : "+f"(d[0]), "+f"(d[1]), "+f"(d[2]), "+f"(d[3])
        : "r"(a[0]), "r"(a[1]), "r"(a[2]), "r"(a[3]), "r"(b[0]), "r"(b[1]));
}
__device__ __forceinline__ void cp16(uint32_t saddr, const void* gaddr) {
    asm volatile("cp.async.cg.shared.global [%0], [%1], 16;" :: "r"(saddr), "l"(gaddr));
}

// ---------- warp reductions ----------
__device__ __forceinline__ float wsum(float v) {
    #pragma unroll
    for (int o = 16; o; o >>= 1) v += __shfl_xor_sync(0xffffffffu, v, o);
    return v;
}
__device__ __forceinline__ void wsum2(float &a, float &b) {
    #pragma unroll
    for (int o = 16; o; o >>= 1) {
        a += __shfl_xor_sync(0xffffffffu, a, o);
        b += __shfl_xor_sync(0xffffffffu, b, o);
    }
}
__device__ __forceinline__ void wsum4(float4 &v) {
    #pragma unroll
    for (int o = 16; o; o >>= 1) {
        v.x += __shfl_xor_sync(0xffffffffu, v.x, o);
        v.y += __shfl_xor_sync(0xffffffffu, v.y, o);
        v.z += __shfl_xor_sync(0xffffffffu, v.z, o);
        v.w += __shfl_xor_sync(0xffffffffu, v.w, o);
    }
}

// ============================================================
// Kernel 0: fp32 -> bf16 hi/lo split (unchanged)
// ============================================================
__global__ __launch_bounds__(256) void convert_kernel(
    const float* __restrict__ A, const float* __restrict__ B)
{
    const size_t NA4 = (size_t)MROWS * DD / 4;
    const size_t NB4 = (size_t)NCOLS * DD / 4;
    size_t t = (size_t)blockIdx.x * 256 + threadIdx.x;
    const float* src;
    __nv_bfloat16 *hi, *lo;
    size_t idx4;
    if (t < NA4)            { src = A; hi = g_ahi; lo = g_alo; idx4 = t; }
    else if (t < NA4 + NB4) { src = B; hi = g_bhi; lo = g_blo; idx4 = t - NA4; }
    else return;
    float4 v = ((const float4*)src)[idx4];
    __nv_bfloat16 h0 = __float2bfloat16_rn(v.x);
    __nv_bfloat16 h1 = __float2bfloat16_rn(v.y);
    __nv_bfloat16 h2 = __float2bfloat16_rn(v.z);
    __nv_bfloat16 h3 = __float2bfloat16_rn(v.w);
    __nv_bfloat16 l0 = __float2bfloat16_rn(v.x - __bfloat162float(h0));
    __nv_bfloat16 l1 = __float2bfloat16_rn(v.y - __bfloat162float(h1));
    __nv_bfloat16 l2 = __float2bfloat16_rn(v.z - __bfloat162float(h2));
    __nv_bfloat16 l3 = __float2bfloat16_rn(v.w - __bfloat162float(h3));
    __nv_bfloat162* hp = (__nv_bfloat162*)(hi + 4 * idx4);
    __nv_bfloat162* lp = (__nv_bfloat162*)(lo + 4 * idx4);
    hp[0] = __nv_bfloat162(h0, h1); hp[1] = __nv_bfloat162(h2, h3);
    lp[0] = __nv_bfloat162(l0, l1); lp[1] = __nv_bfloat162(l2, l3);
}

// ============================================================
// Kernel 1: merged GEMM (BM=128, BN=64, 2-stage, 96KB, 2 blocks/SM)
//           + Gram blocks interleaved (every 10th bid)
// ============================================================
#define TILE_A 16384            // 128 rows x 128B
#define TILE_BT 8192            // 64 rows x 128B
#define STAGE2 (2*TILE_A + 2*TILE_BT)   // 49152 per stage
#define NKT 16

__device__ __forceinline__ void gram_body(int gi, char* smem,
                                          const float* __restrict__ XI,
                                          const float* __restrict__ XC)
{
    float* Xs = (float*)smem;   // 36*132 floats
    const int tid = threadIdx.x;
    if (gi < 128) {
        const int i = gi;
        float acc[3][3];
        #pragma unroll
        for (int a = 0; a < 3; a++)
            #pragma unroll
            for (int b = 0; b < 3; b++) acc[a][b] = 0.f;
        const int r0 = (tid / 12) * 3, c0 = (tid % 12) * 3;
        const bool act = tid < 144;
        const float* base = XI + (size_t)i * RR * DD;
        for (int ch = 0; ch < 8; ch++) {
            for (int f = tid; f < 1152; f += 256) {
                int row = f >> 5, q = f & 31;
                float4 v = *(const float4*)(base + (size_t)row * DD + ch * 128 + q * 4);
                *(float4*)&Xs[row * 132 + q * 4] = v;
            }
            __syncthreads();
            if (act) {
                for (int d = 0; d < 128; d++) {
                    float x0 = Xs[(r0+0)*132+d], x1 = Xs[(r0+1)*132+d], x2 = Xs[(r0+2)*132+d];
                    float y0 = Xs[(c0+0)*132+d], y1 = Xs[(c0+1)*132+d], y2 = Xs[(c0+2)*132+d];
                    acc[0][0] += x0*y0; acc[0][1] += x0*y1; acc[0][2] += x0*y2;
                    acc[1][0] += x1*y0; acc[1][1] += x1*y1; acc[1][2] += x1*y2;
                    acc[2][0] += x2*y0; acc[2][1] += x2*y1; acc[2][2] += x2*y2;
                }
            }
            __syncthreads();
        }
        if (act) {
            float* gp = g_gimg + (size_t)i * (RR * RR);
            #pragma unroll
            for (int a = 0; a < 3; a++)
                #pragma unroll
                for (int b = 0; b < 3; b++)
                    gp[(r0 + a) * RR + (c0 + b)] = acc[a][b];
        }
    } else {
        const int c = gi - 128;
        float acc[4][4];
        #pragma unroll
        for (int a = 0; a < 4; a++)
            #pragma unroll
            for (int b = 0; b < 4; b++) acc[a][b] = 0.f;
        const int r0 = (tid / 8) * 4, c0 = (tid % 8) * 4;
        const bool act = tid < 64;
        const float* base = XC + (size_t)c * WW * DD;
        for (int ch = 0; ch < 8; ch++) {
            for (int f = tid; f < 1024; f += 256) {
                int row = f >> 5, q = f & 31;
                float4 v = *(const float4*)(base + (size_t)row * DD + ch * 128 + q * 4);
                *(float4*)&Xs[row * 132 + q * 4] = v;
            }
            __syncthreads();
            if (act) {
                for (int d = 0; d < 128; d++) {
                    float x0 = Xs[(r0+0)*132+d], x1 = Xs[(r0+1)*132+d];
                    float x2 = Xs[(r0+2)*132+d], x3 = Xs[(r0+3)*132+d];
                    float y0 = Xs[(c0+0)*132+d], y1 = Xs[(c0+1)*132+d];
                    float y2 = Xs[(c0+2)*132+d], y3 = Xs[(c0+3)*132+d];
                    acc[0][0]+=x0*y0; acc[0][1]+=x0*y1; acc[0][2]+=x0*y2; acc[0][3]+=x0*y3;
                    acc[1][0]+=x1*y0; acc[1][1]+=x1*y1; acc[1][2]+=x1*y2; acc[1][3]+=x1*y3;
                    acc[2][0]+=x2*y0; acc[2][1]+=x2*y1; acc[2][2]+=x2*y2; acc[2][3]+=x2*y3;
                    acc[3][0]+=x3*y0; acc[3][1]+=x3*y1; acc[3][2]+=x3*y2; acc[3][3]+=x3*y3;
                }
            }
            __syncthreads();
        }
        if (act) {
            float* gp = g_gcap + (size_t)c * (WW * WW);
            #pragma unroll
            for (int a = 0; a < 4; a++)
                #pragma unroll
                for (int b = 0; b < 4; b++)
                    gp[(r0 + a) * WW + (c0 + b)] = acc[a][b];
        }
    }
}

__global__ __launch_bounds__(256, 2) void gemm_gram(
    const float* __restrict__ XI, const float* __restrict__ XC)
{
    extern __shared__ char smem[];
    const int bid = blockIdx.x;
    if (bid % 10 == 0) {            // 256 gram blocks interleaved
        gram_body(bid / 10, smem, XI, XC);
        return;
    }
    const int gb = bid - bid / 10 - 1;        // 0 .. 2303
    const int bm0 = (gb >> 6) * 128;          // 36 M-tiles
    const int bn0 = (gb & 63) * 64;           // 64 N-tiles

    const uint32_t sb = smem_u32(smem);
    const int tid = threadIdx.x;
    const int wid = tid >> 5, ln = tid & 31;
    const int wm = wid & 3;       // M: 4 x 32 rows
    const int wn = wid >> 2;      // N: 2 x 32 cols

    const int which = tid >> 6;
    const int t64 = tid & 63;
    const __nv_bfloat16* gsrc;
    int row0, nj;
    uint32_t toff;
    if      (which == 0) { gsrc = g_ahi; row0 = bm0; nj = 16; toff = 0; }
    else if (which == 1) { gsrc = g_alo; row0 = bm0; nj = 16; toff = TILE_A; }
    else if (which == 2) { gsrc = g_bhi; row0 = bn0; nj = 8;  toff = 2*TILE_A; }
    else                 { gsrc = g_blo; row0 = bn0; nj = 8;  toff = 2*TILE_A + TILE_BT; }
    const char* gbase = (const char*)gsrc + (size_t)row0 * (DD * 2);
    const uint32_t sbase_w = sb + toff;

    auto issue = [&](int stage, int kt) {
        const char* gp = gbase + (size_t)kt * 128;
        const uint32_t sp = sbase_w + stage * STAGE2;
        for (int j = 0; j < nj; j++) {
            int chunk = t64 + 64 * j;
            int row = chunk >> 3, cc = chunk & 7;
            cp16(sp + swz128(row * 128 + cc * 16),
                 gp + (size_t)row * (DD * 2) + cc * 16);
        }
        asm volatile("cp.async.commit_group;" ::: "memory");
    };

    float acc[2][4][4];
    #pragma unroll
    for (int am = 0; am < 2; am++)
        #pragma unroll
        for (int na = 0; na < 4; na++)
            #pragma unroll
            for (int q = 0; q < 4; q++) acc[am][na][q] = 0.f;

    issue(0, 0);

    const int a_row = (ln & 7) + ((ln >> 3) & 1) * 8;
    const int a_kb  = (ln >> 4) * 16;
    const int b_row = (ln & 7) + (ln >> 4) * 8;
    const int b_kb  = ((ln >> 3) & 1) * 16;

    #pragma unroll 1
    for (int kt = 0; kt < NKT; kt++) {
        if (kt + 1 < NKT) {
            issue((kt + 1) & 1, kt + 1);
            asm volatile("cp.async.wait_group 1;" ::: "memory");
        } else {
            asm volatile("cp.async.wait_group 0;" ::: "memory");
        }
        __syncthreads();

        const uint32_t st = sb + (kt & 1) * STAGE2;
        const uint32_t aHi = st, aLo = st + TILE_A;
        const uint32_t bHi = st + 2*TILE_A, bLo = st + 2*TILE_A + TILE_BT;

        #pragma unroll
        for (int ks = 0; ks < 4; ks++) {
            const int kb = ks * 32;
            uint32_t ah[2][4], al[2][4], bh[4][2], bl[4][2];
            #pragma unroll
            for (int am = 0; am < 2; am++) {
                uint32_t off = swz128((wm * 32 + am * 16 + a_row) * 128 + kb + a_kb);
                ldsm_x4(ah[am], aHi + off);
                ldsm_x4(al[am], aLo + off);
            }
            #pragma unroll
            for (int p = 0; p < 2; p++) {
                uint32_t off = swz128((wn * 32 + p * 16 + b_row) * 128 + kb + b_kb);
                uint32_t r4[4];
                ldsm_x4(r4, bHi + off);
                bh[2*p][0] = r4[0]; bh[2*p][1] = r4[1];
                bh[2*p+1][0] = r4[2]; bh[2*p+1][1] = r4[3];
                ldsm_x4(r4, bLo + off);
                bl[2*p][0] = r4[0]; bl[2*p][1] = r4[1];
                bl[2*p+1][0] = r4[2]; bl[2*p+1][1] = r4[3];
            }
            #pragma unroll
            for (int am = 0; am < 2; am++)
                #pragma unroll
                for (int na = 0; na < 4; na++) {
                    mma16816(acc[am][na], ah[am], bh[na]);
                    mma16816(acc[am][na], ah[am], bl[na]);
                    mma16816(acc[am][na], al[am], bh[na]);
                }
        }
        __syncthreads();
    }

    // epilogue -> g_sim[c][i][r][w]
    const int rq = ln >> 2, cq = (ln & 3) * 2;
    #pragma unroll
    for (int am = 0; am < 2; am++) {
        const int m0 = bm0 + wm * 32 + am * 16 + rq;
        const int m1 = m0 + 8;
        const int i0 = m0 / 36, r0 = m0 - i0 * 36;
        const int i1 = m1 / 36, r1 = m1 - i1 * 36;
        #pragma unroll
        for (int na = 0; na < 4; na++) {
            const int n = bn0 + wn * 32 + na * 8 + cq;
            const int cidx = n >> 5, w = n & 31;
            float* p0 = g_sim + ((size_t)cidx * NI + i0) * (RR * WW) + r0 * WW + w;
            float* p1 = g_sim + ((size_t)cidx * NI + i1) * (RR * WW) + r1 * WW + w;
            float2 v0 = {acc[am][na][0], acc[am][na][1]};
            float2 v1 = {acc[am][na][2], acc[am][na][3]};
            *(float2*)p0 = v0;
            *(float2*)p1 = v1;
        }
    }
}

// ============================================================
// Kernel 4: per-(image,caption) focal attention + cosine (R8 winner)
// ============================================================
__global__ __launch_bounds__(256, 8) void pair_kernel(float* __restrict__ out) {
    const int i = blockIdx.x, c = blockIdx.y;
    __shared__ float M[36 * 33];
    __shared__ float Gi[36 * 37];
    __shared__ float Gc[32 * 33];
    __shared__ __align__(16) float AtP[36 * 36];   // [r][w] row stride 36
    __shared__ __align__(16) float AiP[32 * 36];   // [ww][r] row stride 36
    __shared__ float rinv[36], cinv[32];
    __shared__ float numT[32], numI[36];
    __shared__ float accT, accI;

    const int tid = threadIdx.x;
    if (tid == 0) { accT = 0.f; accI = 0.f; }

    const float* simp = g_sim + ((size_t)c * NI + i) * (RR * WW);
    for (int g = tid; g < RR * WW; g += 256) {
        int r = g >> 5, w = g & 31;
        M[r * 33 + w] = simp[g];
    }
    const float* gip = g_gimg + (size_t)i * (RR * RR);
    for (int g = tid; g < RR * RR; g += 256) {
        int r = g / 36, rr = g % 36;
        Gi[r * 37 + rr] = gip[g];
    }
    const float* gcp = g_gcap + (size_t)c * (WW * WW);
    for (int g = tid; g < WW * WW; g += 256) {
        int w = g >> 5, ww = g & 31;
        Gc[w * 33 + ww] = gcp[g];
    }
    __syncthreads();

    const int wd = tid >> 5, ln = tid & 31;

    // ---- phase 1: inverse norms only (68 scalars) ----
    for (int task = wd; task < 68; task += 8) {
        if (task < 36) {
            int r = task;
            float v = M[r * 33 + ln];
            v = v > 0.f ? v : 0.1f * v;
            float s = wsum(v * v);
            if (ln == 0) rinv[r] = __fdividef(1.f, __fsqrt_rn(s) + 1e-8f);
        } else {
            int w = task - 36;
            float v1 = M[ln * 33 + w];
            v1 = v1 > 0.f ? v1 : 0.1f * v1;
            float v2 = 0.f;
            if (ln < 4) {
                v2 = M[(ln + 32) * 33 + w];
                v2 = v2 > 0.f ? v2 : 0.1f * v2;
            }
            float s = wsum(v1 * v1 + v2 * v2);
            if (ln == 0) cinv[w] = __fdividef(1.f, __fsqrt_rn(s) + 1e-8f);
        }
    }
    __syncthreads();

    // ---- phase 2a: softmax (no max-sub) + focal mask + numerator ----
    for (int task = wd; task < 68; task += 8) {
        if (task < 32) {
            int w = task;
            int r1 = ln, r2 = ln + 32;
            bool h2 = ln < 4;
            float m1 = M[r1 * 33 + w];
            float l1 = (m1 > 0.f ? m1 : 0.1f * m1) * rinv[r1];
            float e1 = __expf(20.f * l1);
            float m2 = 0.f, e2 = 0.f;
            if (h2) {
                m2 = M[r2 * 33 + w];
                float l2 = (m2 > 0.f ? m2 : 0.1f * m2) * rinv[r2];
                e2 = __expf(20.f * l2);
            }
            float s = wsum(e1 + e2);
            bool k1 = 36.f * e1 > s;
            bool k2 = h2 && (36.f * e2 > s);
            float te = (k1 ? e1 : 0.f) + (k2 ? e2 : 0.f);
            float nm = (k1 ? e1 * m1 : 0.f) + (k2 ? e2 * m2 : 0.f);
            wsum2(te, nm);
            float it = __fdividef(1.f, te);
            AtP[r1 * 36 + w] = k1 ? e1 * it : 0.f;
            if (h2) AtP[r2 * 36 + w] = k2 ? e2 * it : 0.f;
            if (ln == 0) numT[w] = nm * it;
        } else {
            int r = task - 32;
            float mv = M[r * 33 + ln];
            float l = (mv > 0.f ? mv : 0.1f * mv) * cinv[ln];
            float e = __expf(20.f * l);
            float s = wsum(e);
            bool k = 32.f * e > s;
            float te = k ? e : 0.f;
            float nm = k ? e * mv : 0.f;
            wsum2(te, nm);
            float it = __fdividef(1.f, te);
            AiP[ln * 36 + r] = k ? e * it : 0.f;
            if (ln == 0) numI[r] = nm * it;
        }
    }
    __syncthreads();

    // ---- phase 2b: batched quadratic forms, 4 queries per sweep ----
    float tAcc = 0.f, iAcc = 0.f;
    for (int t = wd; t < 17; t += 8) {
        if (t < 8) {
            const int w0 = t * 4;
            const bool h2 = ln < 4;
            float4 in1 = {0.f, 0.f, 0.f, 0.f};
            float4 in2 = {0.f, 0.f, 0.f, 0.f};
            const float* giR  = &Gi[ln * 37];
            const float* giR2 = &Gi[(ln + 32) * 37];
            #pragma unroll 6
            for (int rr = 0; rr < 36; rr++) {
                float gv = giR[rr];
                float4 a4 = *(const float4*)&AtP[rr * 36 + w0];
                in1.x = fmaf(gv, a4.x, in1.x);
                in1.y = fmaf(gv, a4.y, in1.y);
                in1.z = fmaf(gv, a4.z, in1.z);
                in1.w = fmaf(gv, a4.w, in1.w);
                if (h2) {
                    float gv2 = giR2[rr];
                    in2.x = fmaf(gv2, a4.x, in2.x);
                    in2.y = fmaf(gv2, a4.y, in2.y);
                    in2.z = fmaf(gv2, a4.z, in2.z);
                    in2.w = fmaf(gv2, a4.w, in2.w);
                }
            }
            float4 at1 = *(const float4*)&AtP[ln * 36 + w0];
            float4 at2 = {0.f, 0.f, 0.f, 0.f};
            if (h2) at2 = *(const float4*)&AtP[(ln + 32) * 36 + w0];
            float4 d;
            d.x = at1.x * in1.x + at2.x * in2.x;
            d.y = at1.y * in1.y + at2.y * in2.y;
            d.z = at1.z * in1.z + at2.z * in2.z;
            d.w = at1.w * in1.w + at2.w * in2.w;
            wsum4(d);
            #pragma unroll
            for (int q = 0; q < 4; q++) {
                float d2 = fmaxf((&d.x)[q], 1e-16f);
                float gd = fmaxf(Gc[(w0 + q) * 33 + (w0 + q)], 1e-16f);
                tAcc += numT[w0 + q] * __frsqrt_rn(d2) * __frsqrt_rn(gd);
            }
        } else {
            const int r0 = (t - 8) * 4;
            float4 in = {0.f, 0.f, 0.f, 0.f};
            const float* gcR = &Gc[ln * 33];
            #pragma unroll 8
            for (int ww = 0; ww < 32; ww++) {
                float gv = gcR[ww];
                float4 a4 = *(const float4*)&AiP[ww * 36 + r0];
                in.x = fmaf(gv, a4.x, in.x);
                in.y = fmaf(gv, a4.y, in.y);
                in.z = fmaf(gv, a4.z, in.z);
                in.w = fmaf(gv, a4.w, in.w);
            }
            float4 at = *(const float4*)&AiP[ln * 36 + r0];
            float4 d;
            d.x = at.x * in.x;
            d.y = at.y * in.y;
            d.z = at.z * in.z;
            d.w = at.w * in.w;
            wsum4(d);
            #pragma unroll
            for (int q = 0; q < 4; q++) {
                float d2 = fmaxf((&d.x)[q], 1e-16f);
                float gd = fmaxf(Gi[(r0 + q) * 37 + (r0 + q)], 1e-16f);
                iAcc += numI[r0 + q] * __frsqrt_rn(d2) * __frsqrt_rn(gd);
            }
        }
    }
    if (ln == 0) {
        atomicAdd(&accT, tAcc);
        atomicAdd(&accI, iAcc);
    }
    __syncthreads();
    if (tid == 0) out[(size_t)i * NC + c] = accT * (1.f / 32.f) + accI * (1.f / 36.f);
}

// ============================================================
extern "C" void kernel_launch(void* const* d_in, const int* in_sizes, int n_in,
                              void* d_out, int out_size) {
    const float* images   = (const float*)d_in[0];
    const float* captions = (const float*)d_in[1];
    float* out = (float*)d_out;

    const int SMEM_TOTAL = 2 * STAGE2;   // 96 KB -> 2 blocks/SM
    cudaFuncSetAttribute(gemm_gram, cudaFuncAttributeMaxDynamicSharedMemorySize, SMEM_TOTAL);

    const size_t n4 = ((size_t)MROWS * DD + (size_t)NCOLS * DD) / 4;
    convert_kernel<<<(unsigned)((n4 + 255) / 256), 256>>>(images, captions);
    gemm_gram<<<2560, 256, SMEM_TOTAL>>>(images, captions);   // 2304 gemm + 256 gram
    pair_kernel<<<dim3(128, 128), 256>>>(out);
}

// round 11
// speedup vs baseline: 1.0346x; 1.0346x over previous
#include <cuda_runtime.h>
#include <cuda_bf16.h>
#include <cstdint>

#define NI 128
#define NC 128
#define RR 36
#define WW 32
#define DD 1024
#define MROWS (NI*RR)   // 4608
#define NCOLS (NC*WW)   // 4096

// Scratch (allocation-free contract: __device__ globals)
__device__ float g_sim[(size_t)NC * NI * RR * WW];   // [c][i][r][w]
__device__ float g_gimg[(size_t)NI * RR * RR];
__device__ float g_gcap[(size_t)NC * WW * WW];
__device__ __nv_bfloat16 g_ahi[(size_t)MROWS * DD];
__device__ __nv_bfloat16 g_alo[(size_t)MROWS * DD];
__device__ __nv_bfloat16 g_bhi[(size_t)NCOLS * DD];
__device__ __nv_bfloat16 g_blo[(size_t)NCOLS * DD];

// ---------------- helpers ----------------
__device__ __forceinline__ uint32_t smem_u32(const void* p) {
    uint32_t a;
    asm("{ .reg .u64 t; cvta.to.shared.u64 t, %1; cvt.u32.u64 %0, t; }" : "=r"(a) : "l"(p));
    return a;
}
__device__ __forceinline__ uint32_t swz128(uint32_t off) { return off ^ ((off >> 3) & 0x70); }

__device__ __forceinline__ void ldsm_x4(uint32_t* r, uint32_t addr) {
    asm volatile("ldmatrix.sync.aligned.m8n8.x4.shared.b16 {%0,%1,%2,%3}, [%4];"
                 : "=r"(r[0]), "=r"(r[1]), "=r"(r[2]), "=r"(r[3]) : "r"(addr));
}
__device__ __forceinline__ void mma16816(float* d, const uint32_t* a, const uint32_t* b) {
    asm volatile(
        "mma.sync.aligned.m16n8k16.row.col.f32.bf16.bf16.f32 "
        "{%0,%1,%2,%3}, {%4,%5,%6,%7}, {%8,%9}, {%0,%1,%2,%3};"
        : "+f"(d[0]), "+f"(d[1]), "+f"(d[2]), "+f"(d[3])
        : "r"(a[0]), "r"(a[1]), "r"(a[2]), "r"(a[3]), "r"(b[0]), "r"(b[1]));
}
__device__ __forceinline__ void cp16(uint32_t saddr, const void* gaddr) {
    asm volatile("cp.async.cg.shared.global [%0], [%1], 16;" :: "r"(saddr), "l"(gaddr));
}

// ---------- warp reductions ----------
__device__ __forceinline__ float wsum(float v) {
    #pragma unroll
    for (int o = 16; o; o >>= 1) v += __shfl_xor_sync(0xffffffffu, v, o);
    return v;
}
__device__ __forceinline__ void wsum2(float &a, float &b) {
    #pragma unroll
    for (int o = 16; o; o >>= 1) {
        a += __shfl_xor_sync(0xffffffffu, a, o);
        b += __shfl_xor_sync(0xffffffffu, b, o);
    }
}
__device__ __forceinline__ void wsum4(float4 &v) {
    #pragma unroll
    for (int o = 16; o; o >>= 1) {
        v.x += __shfl_xor_sync(0xffffffffu, v.x, o);
        v.y += __shfl_xor_sync(0xffffffffu, v.y, o);
        v.z += __shfl_xor_sync(0xffffffffu, v.z, o);
        v.w += __shfl_xor_sync(0xffffffffu, v.w, o);
    }
}

// ============================================================
// Kernel 0: fused prep — gram blocks (0..255) + convert blocks
// gram depends only on raw inputs; convert only feeds gemm.
// Running them concurrently removes their serialization.
// ============================================================
__global__ __launch_bounds__(256) void prep_kernel(
    const float* __restrict__ XI, const float* __restrict__ XC)
{
    __shared__ float Xs[36 * 132];
    const int tid = threadIdx.x;
    const int bid = blockIdx.x;

    if (bid < 128) {
        // ---- image Gram ----
        const int i = bid;
        float acc[3][3];
        #pragma unroll
        for (int a = 0; a < 3; a++)
            #pragma unroll
            for (int b = 0; b < 3; b++) acc[a][b] = 0.f;
        const int r0 = (tid / 12) * 3, c0 = (tid % 12) * 3;
        const bool act = tid < 144;
        const float* base = XI + (size_t)i * RR * DD;
        for (int ch = 0; ch < 8; ch++) {
            for (int f = tid; f < 1152; f += 256) {
                int row = f >> 5, q = f & 31;
                float4 v = *(const float4*)(base + (size_t)row * DD + ch * 128 + q * 4);
                *(float4*)&Xs[row * 132 + q * 4] = v;
            }
            __syncthreads();
            if (act) {
                for (int d = 0; d < 128; d++) {
                    float x0 = Xs[(r0+0)*132+d], x1 = Xs[(r0+1)*132+d], x2 = Xs[(r0+2)*132+d];
                    float y0 = Xs[(c0+0)*132+d], y1 = Xs[(c0+1)*132+d], y2 = Xs[(c0+2)*132+d];
                    acc[0][0] += x0*y0; acc[0][1] += x0*y1; acc[0][2] += x0*y2;
                    acc[1][0] += x1*y0; acc[1][1] += x1*y1; acc[1][2] += x1*y2;
                    acc[2][0] += x2*y0; acc[2][1] += x2*y1; acc[2][2] += x2*y2;
                }
            }
            __syncthreads();
        }
        if (act) {
            float* gp = g_gimg + (size_t)i * (RR * RR);
            #pragma unroll
            for (int a = 0; a < 3; a++)
                #pragma unroll
                for (int b = 0; b < 3; b++)
                    gp[(r0 + a) * RR + (c0 + b)] = acc[a][b];
        }
    } else if (bid < 256) {
        // ---- caption Gram ----
        const int c = bid - 128;
        float acc[4][4];
        #pragma unroll
        for (int a = 0; a < 4; a++)
            #pragma unroll
            for (int b = 0; b < 4; b++) acc[a][b] = 0.f;
        const int r0 = (tid / 8) * 4, c0 = (tid % 8) * 4;
        const bool act = tid < 64;
        const float* base = XC + (size_t)c * WW * DD;
        for (int ch = 0; ch < 8; ch++) {
            for (int f = tid; f < 1024; f += 256) {
                int row = f >> 5, q = f & 31;
                float4 v = *(const float4*)(base + (size_t)row * DD + ch * 128 + q * 4);
                *(float4*)&Xs[row * 132 + q * 4] = v;
            }
            __syncthreads();
            if (act) {
                for (int d = 0; d < 128; d++) {
                    float x0 = Xs[(r0+0)*132+d], x1 = Xs[(r0+1)*132+d];
                    float x2 = Xs[(r0+2)*132+d], x3 = Xs[(r0+3)*132+d];
                    float y0 = Xs[(c0+0)*132+d], y1 = Xs[(c0+1)*132+d];
                    float y2 = Xs[(c0+2)*132+d], y3 = Xs[(c0+3)*132+d];
                    acc[0][0]+=x0*y0; acc[0][1]+=x0*y1; acc[0][2]+=x0*y2; acc[0][3]+=x0*y3;
                    acc[1][0]+=x1*y0; acc[1][1]+=x1*y1; acc[1][2]+=x1*y2; acc[1][3]+=x1*y3;
                    acc[2][0]+=x2*y0; acc[2][1]+=x2*y1; acc[2][2]+=x2*y2; acc[2][3]+=x2*y3;
                    acc[3][0]+=x3*y0; acc[3][1]+=x3*y1; acc[3][2]+=x3*y2; acc[3][3]+=x3*y3;
                }
            }
            __syncthreads();
        }
        if (act) {
            float* gp = g_gcap + (size_t)c * (WW * WW);
            #pragma unroll
            for (int a = 0; a < 4; a++)
                #pragma unroll
                for (int b = 0; b < 4; b++)
                    gp[(r0 + a) * WW + (c0 + b)] = acc[a][b];
        }
    } else {
        // ---- fp32 -> bf16 hi/lo split ----
        const size_t NA4 = (size_t)MROWS * DD / 4;
        const size_t NB4 = (size_t)NCOLS * DD / 4;
        size_t t = (size_t)(bid - 256) * 256 + tid;
        const float* src;
        __nv_bfloat16 *hi, *lo;
        size_t idx4;
        if (t < NA4)            { src = XI; hi = g_ahi; lo = g_alo; idx4 = t; }
        else if (t < NA4 + NB4) { src = XC; hi = g_bhi; lo = g_blo; idx4 = t - NA4; }
        else return;
        float4 v = ((const float4*)src)[idx4];
        __nv_bfloat16 h0 = __float2bfloat16_rn(v.x);
        __nv_bfloat16 h1 = __float2bfloat16_rn(v.y);
        __nv_bfloat16 h2 = __float2bfloat16_rn(v.z);
        __nv_bfloat16 h3 = __float2bfloat16_rn(v.w);
        __nv_bfloat16 l0 = __float2bfloat16_rn(v.x - __bfloat162float(h0));
        __nv_bfloat16 l1 = __float2bfloat16_rn(v.y - __bfloat162float(h1));
        __nv_bfloat16 l2 = __float2bfloat16_rn(v.z - __bfloat162float(h2));
        __nv_bfloat16 l3 = __float2bfloat16_rn(v.w - __bfloat162float(h3));
        __nv_bfloat162* hp = (__nv_bfloat162*)(hi + 4 * idx4);
        __nv_bfloat162* lp = (__nv_bfloat162*)(lo + 4 * idx4);
        hp[0] = __nv_bfloat162(h0, h1); hp[1] = __nv_bfloat162(h2, h3);
        lp[0] = __nv_bfloat162(l0, l1); lp[1] = __nv_bfloat162(l2, l3);
    }
}

// ============================================================
// Kernel 1: bf16 mma.sync similarity GEMM, 3-stage cp.async pipe
// (exact R8 winner)
// ============================================================
#define TILE_B 16384
#define STAGE_B (4 * TILE_B)
#define NKT 16

__global__ __launch_bounds__(256, 1) void gemm_mma(void) {
    extern __shared__ char smem[];
    const uint32_t sb = smem_u32(smem);
    const int tid = threadIdx.x;
    const int wid = tid >> 5, ln = tid & 31;
    const int bm0 = blockIdx.y * 128;
    const int bn0 = blockIdx.x * 128;
    const int wm = wid & 3;
    const int wn = wid >> 2;

    const int which = tid >> 6;
    const int t64 = tid & 63;
    const __nv_bfloat16* gsrc;
    int row0;
    if      (which == 0) { gsrc = g_ahi; row0 = bm0; }
    else if (which == 1) { gsrc = g_alo; row0 = bm0; }
    else if (which == 2) { gsrc = g_bhi; row0 = bn0; }
    else                 { gsrc = g_blo; row0 = bn0; }
    const char* gbase = (const char*)gsrc + (size_t)row0 * (DD * 2);
    const uint32_t sbase_w = sb + which * TILE_B;

    auto issue = [&](int stage, int kt) {
        const char* gp = gbase + (size_t)kt * 128;
        const uint32_t sp = sbase_w + stage * STAGE_B;
        #pragma unroll
        for (int j = 0; j < 16; j++) {
            int chunk = t64 + 64 * j;
            int row = chunk >> 3, cc = chunk & 7;
            cp16(sp + swz128(row * 128 + cc * 16),
                 gp + (size_t)row * (DD * 2) + cc * 16);
        }
        asm volatile("cp.async.commit_group;" ::: "memory");
    };

    float acc[2][8][4];
    #pragma unroll
    for (int am = 0; am < 2; am++)
        #pragma unroll
        for (int na = 0; na < 8; na++)
            #pragma unroll
            for (int q = 0; q < 4; q++) acc[am][na][q] = 0.f;

    issue(0, 0);
    issue(1, 1);

    const int a_row = (ln & 7) + ((ln >> 3) & 1) * 8;
    const int a_kb  = (ln >> 4) * 16;
    const int b_row = (ln & 7) + (ln >> 4) * 8;
    const int b_kb  = ((ln >> 3) & 1) * 16;

    int stage = 0;
    #pragma unroll 1
    for (int kt = 0; kt < NKT; kt++) {
        if (kt + 2 < NKT) {
            asm volatile("cp.async.wait_group 1;" ::: "memory");
        } else {
            asm volatile("cp.async.wait_group 0;" ::: "memory");
        }
        __syncthreads();
        if (kt + 2 < NKT) {
            int ns = stage + 2; if (ns >= 3) ns -= 3;
            issue(ns, kt + 2);
        }

        const uint32_t st = sb + stage * STAGE_B;
        const uint32_t aHi = st, aLo = st + TILE_B;
        const uint32_t bHi = st + 2 * TILE_B, bLo = st + 3 * TILE_B;

        #pragma unroll
        for (int ks = 0; ks < 4; ks++) {
            const int kb = ks * 32;
            uint32_t ah[2][4], al[2][4], bh[8][2], bl[8][2];
            #pragma unroll
            for (int am = 0; am < 2; am++) {
                uint32_t off = swz128((wm * 32 + am * 16 + a_row) * 128 + kb + a_kb);
                ldsm_x4(ah[am], aHi + off);
                ldsm_x4(al[am], aLo + off);
            }
            #pragma unroll
            for (int p = 0; p < 4; p++) {
                uint32_t off = swz128((wn * 64 + p * 16 + b_row) * 128 + kb + b_kb);
                uint32_t r4[4];
                ldsm_x4(r4, bHi + off);
                bh[2*p][0] = r4[0]; bh[2*p][1] = r4[1];
                bh[2*p+1][0] = r4[2]; bh[2*p+1][1] = r4[3];
                ldsm_x4(r4, bLo + off);
                bl[2*p][0] = r4[0]; bl[2*p][1] = r4[1];
                bl[2*p+1][0] = r4[2]; bl[2*p+1][1] = r4[3];
            }
            #pragma unroll
            for (int am = 0; am < 2; am++)
                #pragma unroll
                for (int na = 0; na < 8; na++) {
                    mma16816(acc[am][na], ah[am], bh[na]);
                    mma16816(acc[am][na], ah[am], bl[na]);
                    mma16816(acc[am][na], al[am], bh[na]);
                }
        }
        __syncthreads();
        stage++; if (stage >= 3) stage = 0;
    }

    const int rq = ln >> 2, cq = (ln & 3) * 2;
    #pragma unroll
    for (int am = 0; am < 2; am++) {
        const int m0 = bm0 + wm * 32 + am * 16 + rq;
        const int m1 = m0 + 8;
        const int i0 = m0 / 36, r0 = m0 - i0 * 36;
        const int i1 = m1 / 36, r1 = m1 - i1 * 36;
        #pragma unroll
        for (int na = 0; na < 8; na++) {
            const int n = bn0 + wn * 64 + na * 8 + cq;
            const int cidx = n >> 5, w = n & 31;
            float* p0 = g_sim + ((size_t)cidx * NI + i0) * (RR * WW) + r0 * WW + w;
            float* p1 = g_sim + ((size_t)cidx * NI + i1) * (RR * WW) + r1 * WW + w;
            float2 v0 = {acc[am][na][0], acc[am][na][1]};
            float2 v1 = {acc[am][na][2], acc[am][na][3]};
            *(float2*)p0 = v0;
            *(float2*)p1 = v1;
        }
    }
}

// ============================================================
// Kernel 4: per-(image,caption) focal attention + cosine (R8 winner)
// ============================================================
__global__ __launch_bounds__(256, 8) void pair_kernel(float* __restrict__ out) {
    const int i = blockIdx.x, c = blockIdx.y;
    __shared__ float M[36 * 33];
    __shared__ float Gi[36 * 37];
    __shared__ float Gc[32 * 33];
    __shared__ __align__(16) float AtP[36 * 36];   // [r][w] row stride 36
    __shared__ __align__(16) float AiP[32 * 36];   // [ww][r] row stride 36
    __shared__ float rinv[36], cinv[32];
    __shared__ float numT[32], numI[36];
    __shared__ float accT, accI;

    const int tid = threadIdx.x;
    if (tid == 0) { accT = 0.f; accI = 0.f; }

    const float* simp = g_sim + ((size_t)c * NI + i) * (RR * WW);
    for (int g = tid; g < RR * WW; g += 256) {
        int r = g >> 5, w = g & 31;
        M[r * 33 + w] = simp[g];
    }
    const float* gip = g_gimg + (size_t)i * (RR * RR);
    for (int g = tid; g < RR * RR; g += 256) {
        int r = g / 36, rr = g % 36;
        Gi[r * 37 + rr] = gip[g];
    }
    const float* gcp = g_gcap + (size_t)c * (WW * WW);
    for (int g = tid; g < WW * WW; g += 256) {
        int w = g >> 5, ww = g & 31;
        Gc[w * 33 + ww] = gcp[g];
    }
    __syncthreads();

    const int wd = tid >> 5, ln = tid & 31;

    // ---- phase 1: inverse norms only (68 scalars) ----
    for (int task = wd; task < 68; task += 8) {
        if (task < 36) {
            int r = task;
            float v = M[r * 33 + ln];
            v = v > 0.f ? v : 0.1f * v;
            float s = wsum(v * v);
            if (ln == 0) rinv[r] = __fdividef(1.f, __fsqrt_rn(s) + 1e-8f);
        } else {
            int w = task - 36;
            float v1 = M[ln * 33 + w];
            v1 = v1 > 0.f ? v1 : 0.1f * v1;
            float v2 = 0.f;
            if (ln < 4) {
                v2 = M[(ln + 32) * 33 + w];
                v2 = v2 > 0.f ? v2 : 0.1f * v2;
            }
            float s = wsum(v1 * v1 + v2 * v2);
            if (ln == 0) cinv[w] = __fdividef(1.f, __fsqrt_rn(s) + 1e-8f);
        }
    }
    __syncthreads();

    // ---- phase 2a: softmax (no max-sub) + focal mask + numerator ----
    for (int task = wd; task < 68; task += 8) {
        if (task < 32) {
            int w = task;
            int r1 = ln, r2 = ln + 32;
            bool h2 = ln < 4;
            float m1 = M[r1 * 33 + w];
            float l1 = (m1 > 0.f ? m1 : 0.1f * m1) * rinv[r1];
            float e1 = __expf(20.f * l1);
            float m2 = 0.f, e2 = 0.f;
            if (h2) {
                m2 = M[r2 * 33 + w];
                float l2 = (m2 > 0.f ? m2 : 0.1f * m2) * rinv[r2];
                e2 = __expf(20.f * l2);
            }
            float s = wsum(e1 + e2);
            bool k1 = 36.f * e1 > s;
            bool k2 = h2 && (36.f * e2 > s);
            float te = (k1 ? e1 : 0.f) + (k2 ? e2 : 0.f);
            float nm = (k1 ? e1 * m1 : 0.f) + (k2 ? e2 * m2 : 0.f);
            wsum2(te, nm);
            float it = __fdividef(1.f, te);
            AtP[r1 * 36 + w] = k1 ? e1 * it : 0.f;
            if (h2) AtP[r2 * 36 + w] = k2 ? e2 * it : 0.f;
            if (ln == 0) numT[w] = nm * it;
        } else {
            int r = task - 32;
            float mv = M[r * 33 + ln];
            float l = (mv > 0.f ? mv : 0.1f * mv) * cinv[ln];
            float e = __expf(20.f * l);
            float s = wsum(e);
            bool k = 32.f * e > s;
            float te = k ? e : 0.f;
            float nm = k ? e * mv : 0.f;
            wsum2(te, nm);
            float it = __fdividef(1.f, te);
            AiP[ln * 36 + r] = k ? e * it : 0.f;
            if (ln == 0) numI[r] = nm * it;
        }
    }
    __syncthreads();

    // ---- phase 2b: batched quadratic forms, 4 queries per sweep ----
    float tAcc = 0.f, iAcc = 0.f;
    for (int t = wd; t < 17; t += 8) {
        if (t < 8) {
            const int w0 = t * 4;
            const bool h2 = ln < 4;
            float4 in1 = {0.f, 0.f, 0.f, 0.f};
            float4 in2 = {0.f, 0.f, 0.f, 0.f};
            const float* giR  = &Gi[ln * 37];
            const float* giR2 = &Gi[(ln + 32) * 37];
            #pragma unroll 6
            for (int rr = 0; rr < 36; rr++) {
                float gv = giR[rr];
                float4 a4 = *(const float4*)&AtP[rr * 36 + w0];
                in1.x = fmaf(gv, a4.x, in1.x);
                in1.y = fmaf(gv, a4.y, in1.y);
                in1.z = fmaf(gv, a4.z, in1.z);
                in1.w = fmaf(gv, a4.w, in1.w);
                if (h2) {
                    float gv2 = giR2[rr];
                    in2.x = fmaf(gv2, a4.x, in2.x);
                    in2.y = fmaf(gv2, a4.y, in2.y);
                    in2.z = fmaf(gv2, a4.z, in2.z);
                    in2.w = fmaf(gv2, a4.w, in2.w);
                }
            }
            float4 at1 = *(const float4*)&AtP[ln * 36 + w0];
            float4 at2 = {0.f, 0.f, 0.f, 0.f};
            if (h2) at2 = *(const float4*)&AtP[(ln + 32) * 36 + w0];
            float4 d;
            d.x = at1.x * in1.x + at2.x * in2.x;
            d.y = at1.y * in1.y + at2.y * in2.y;
            d.z = at1.z * in1.z + at2.z * in2.z;
            d.w = at1.w * in1.w + at2.w * in2.w;
            wsum4(d);
            #pragma unroll
            for (int q = 0; q < 4; q++) {
                float d2 = fmaxf((&d.x)[q], 1e-16f);
                float gd = fmaxf(Gc[(w0 + q) * 33 + (w0 + q)], 1e-16f);
                tAcc += numT[w0 + q] * __frsqrt_rn(d2) * __frsqrt_rn(gd);
            }
        } else {
            const int r0 = (t - 8) * 4;
            float4 in = {0.f, 0.f, 0.f, 0.f};
            const float* gcR = &Gc[ln * 33];
            #pragma unroll 8
            for (int ww = 0; ww < 32; ww++) {
                float gv = gcR[ww];
                float4 a4 = *(const float4*)&AiP[ww * 36 + r0];
                in.x = fmaf(gv, a4.x, in.x);
                in.y = fmaf(gv, a4.y, in.y);
                in.z = fmaf(gv, a4.z, in.z);
                in.w = fmaf(gv, a4.w, in.w);
            }
            float4 at = *(const float4*)&AiP[ln * 36 + r0];
            float4 d;
            d.x = at.x * in.x;
            d.y = at.y * in.y;
            d.z = at.z * in.z;
            d.w = at.w * in.w;
            wsum4(d);
            #pragma unroll
            for (int q = 0; q < 4; q++) {
                float d2 = fmaxf((&d.x)[q], 1e-16f);
                float gd = fmaxf(Gi[(r0 + q) * 37 + (r0 + q)], 1e-16f);
                iAcc += numI[r0 + q] * __frsqrt_rn(d2) * __frsqrt_rn(gd);
            }
        }
    }
    if (ln == 0) {
        atomicAdd(&accT, tAcc);
        atomicAdd(&accI, iAcc);
    }
    __syncthreads();
    if (tid == 0) out[(size_t)i * NC + c] = accT * (1.f / 32.f) + accI * (1.f / 36.f);
}

// ============================================================
extern "C" void kernel_launch(void* const* d_in, const int* in_sizes, int n_in,
                              void* d_out, int out_size) {
    const float* images   = (const float*)d_in[0];
    const float* captions = (const float*)d_in[1];
    float* out = (float*)d_out;

    const int SMEM_TOTAL = 3 * STAGE_B;   // 192 KB
    cudaFuncSetAttribute(gemm_mma, cudaFuncAttributeMaxDynamicSharedMemorySize, SMEM_TOTAL);

    const size_t n4 = ((size_t)MROWS * DD + (size_t)NCOLS * DD) / 4;
    const unsigned conv_blocks = (unsigned)((n4 + 255) / 256);   // 8704
    prep_kernel<<<conv_blocks + 256, 256>>>(images, captions);   // gram first, convert after
    gemm_mma<<<dim3(32, 36), 256, SMEM_TOTAL>>>();
    pair_kernel<<<dim3(128, 128), 256>>>(out);
}

// round 14
// speedup vs baseline: 1.1801x; 1.1406x over previous
#include <cuda_runtime.h>
#include <cuda_bf16.h>
#include <cstdint>

#define NI 128
#define NC 128
#define RR 36
#define WW 32
#define DD 1024
#define MROWS (NI*RR)   // 4608
#define NCOLS (NC*WW)   // 4096

// Scratch (allocation-free contract: __device__ globals)
__device__ float g_sim[(size_t)NC * NI * RR * WW];   // [c][i][r][w]
__device__ float g_gimg[(size_t)NI * RR * RR];
__device__ float g_gcap[(size_t)NC * WW * WW];
__device__ __nv_bfloat16 g_ahi[(size_t)MROWS * DD];
__device__ __nv_bfloat16 g_alo[(size_t)MROWS * DD];
__device__ __nv_bfloat16 g_bhi[(size_t)NCOLS * DD];
__device__ __nv_bfloat16 g_blo[(size_t)NCOLS * DD];

// ---------------- helpers ----------------
__device__ __forceinline__ uint32_t smem_u32(const void* p) {
    uint32_t a;
    asm("{ .reg .u64 t; cvta.to.shared.u64 t, %1; cvt.u32.u64 %0, t; }" : "=r"(a) : "l"(p));
    return a;
}
__device__ __forceinline__ uint32_t swz128(uint32_t off) { return off ^ ((off >> 3) & 0x70); }

__device__ __forceinline__ void ldsm_x4(uint32_t* r, uint32_t addr) {
    asm volatile("ldmatrix.sync.aligned.m8n8.x4.shared.b16 {%0,%1,%2,%3}, [%4];"
                 : "=r"(r[0]), "=r"(r[1]), "=r"(r[2]), "=r"(r[3]) : "r"(addr));
}
__device__ __forceinline__ void mma16816(float* d, const uint32_t* a, const uint32_t* b) {
    asm volatile(
        "mma.sync.aligned.m16n8k16.row.col.f32.bf16.bf16.f32 "
        "{%0,%1,%2,%3}, {%4,%5,%6,%7}, {%8,%9}, {%0,%1,%2,%3};"
        : "+f"(d[0]), "+f"(d[1]), "+f"(d[2]), "+f"(d[3])
        : "r"(a[0]), "r"(a[1]), "r"(a[2]), "r"(a[3]), "r"(b[0]), "r"(b[1]));
}
__device__ __forceinline__ void cp16(uint32_t saddr, const void* gaddr) {
    asm volatile("cp.async.cg.shared.global [%0], [%1], 16;" :: "r"(saddr), "l"(gaddr));
}

// ---------- warp reductions (phase 2b only) ----------
__device__ __forceinline__ void wsum4(float4 &v) {
    #pragma unroll
    for (int o = 16; o; o >>= 1) {
        v.x += __shfl_xor_sync(0xffffffffu, v.x, o);
        v.y += __shfl_xor_sync(0xffffffffu, v.y, o);
        v.z += __shfl_xor_sync(0xffffffffu, v.z, o);
        v.w += __shfl_xor_sync(0xffffffffu, v.w, o);
    }
}

// ============================================================
// Kernel 0: fused prep — gram blocks (0..255) + convert blocks
// ============================================================
__global__ __launch_bounds__(256) void prep_kernel(
    const float* __restrict__ XI, const float* __restrict__ XC)
{
    __shared__ float Xs[36 * 132];
    const int tid = threadIdx.x;
    const int bid = blockIdx.x;

    if (bid < 128) {
        // ---- image Gram ----
        const int i = bid;
        float acc[3][3];
        #pragma unroll
        for (int a = 0; a < 3; a++)
            #pragma unroll
            for (int b = 0; b < 3; b++) acc[a][b] = 0.f;
        const int r0 = (tid / 12) * 3, c0 = (tid % 12) * 3;
        const bool act = tid < 144;
        const float* base = XI + (size_t)i * RR * DD;
        for (int ch = 0; ch < 8; ch++) {
            for (int f = tid; f < 1152; f += 256) {
                int row = f >> 5, q = f & 31;
                float4 v = *(const float4*)(base + (size_t)row * DD + ch * 128 + q * 4);
                *(float4*)&Xs[row * 132 + q * 4] = v;
            }
            __syncthreads();
            if (act) {
                for (int d = 0; d < 128; d++) {
                    float x0 = Xs[(r0+0)*132+d], x1 = Xs[(r0+1)*132+d], x2 = Xs[(r0+2)*132+d];
                    float y0 = Xs[(c0+0)*132+d], y1 = Xs[(c0+1)*132+d], y2 = Xs[(c0+2)*132+d];
                    acc[0][0] += x0*y0; acc[0][1] += x0*y1; acc[0][2] += x0*y2;
                    acc[1][0] += x1*y0; acc[1][1] += x1*y1; acc[1][2] += x1*y2;
                    acc[2][0] += x2*y0; acc[2][1] += x2*y1; acc[2][2] += x2*y2;
                }
            }
            __syncthreads();
        }
        if (act) {
            float* gp = g_gimg + (size_t)i * (RR * RR);
            #pragma unroll
            for (int a = 0; a < 3; a++)
                #pragma unroll
                for (int b = 0; b < 3; b++)
                    gp[(r0 + a) * RR + (c0 + b)] = acc[a][b];
        }
    } else if (bid < 256) {
        // ---- caption Gram ----
        const int c = bid - 128;
        float acc[4][4];
        #pragma unroll
        for (int a = 0; a < 4; a++)
            #pragma unroll
            for (int b = 0; b < 4; b++) acc[a][b] = 0.f;
        const int r0 = (tid / 8) * 4, c0 = (tid % 8) * 4;
        const bool act = tid < 64;
        const float* base = XC + (size_t)c * WW * DD;
        for (int ch = 0; ch < 8; ch++) {
            for (int f = tid; f < 1024; f += 256) {
                int row = f >> 5, q = f & 31;
                float4 v = *(const float4*)(base + (size_t)row * DD + ch * 128 + q * 4);
                *(float4*)&Xs[row * 132 + q * 4] = v;
            }
            __syncthreads();
            if (act) {
                for (int d = 0; d < 128; d++) {
                    float x0 = Xs[(r0+0)*132+d], x1 = Xs[(r0+1)*132+d];
                    float x2 = Xs[(r0+2)*132+d], x3 = Xs[(r0+3)*132+d];
                    float y0 = Xs[(c0+0)*132+d], y1 = Xs[(c0+1)*132+d];
                    float y2 = Xs[(c0+2)*132+d], y3 = Xs[(c0+3)*132+d];
                    acc[0][0]+=x0*y0; acc[0][1]+=x0*y1; acc[0][2]+=x0*y2; acc[0][3]+=x0*y3;
                    acc[1][0]+=x1*y0; acc[1][1]+=x1*y1; acc[1][2]+=x1*y2; acc[1][3]+=x1*y3;
                    acc[2][0]+=x2*y0; acc[2][1]+=x2*y1; acc[2][2]+=x2*y2; acc[2][3]+=x2*y3;
                    acc[3][0]+=x3*y0; acc[3][1]+=x3*y1; acc[3][2]+=x3*y2; acc[3][3]+=x3*y3;
                }
            }
            __syncthreads();
        }
        if (act) {
            float* gp = g_gcap + (size_t)c * (WW * WW);
            #pragma unroll
            for (int a = 0; a < 4; a++)
                #pragma unroll
                for (int b = 0; b < 4; b++)
                    gp[(r0 + a) * WW + (c0 + b)] = acc[a][b];
        }
    } else {
        // ---- fp32 -> bf16 hi/lo split ----
        const size_t NA4 = (size_t)MROWS * DD / 4;
        const size_t NB4 = (size_t)NCOLS * DD / 4;
        size_t t = (size_t)(bid - 256) * 256 + tid;
        const float* src;
        __nv_bfloat16 *hi, *lo;
        size_t idx4;
        if (t < NA4)            { src = XI; hi = g_ahi; lo = g_alo; idx4 = t; }
        else if (t < NA4 + NB4) { src = XC; hi = g_bhi; lo = g_blo; idx4 = t - NA4; }
        else return;
        float4 v = ((const float4*)src)[idx4];
        __nv_bfloat16 h0 = __float2bfloat16_rn(v.x);
        __nv_bfloat16 h1 = __float2bfloat16_rn(v.y);
        __nv_bfloat16 h2 = __float2bfloat16_rn(v.z);
        __nv_bfloat16 h3 = __float2bfloat16_rn(v.w);
        __nv_bfloat16 l0 = __float2bfloat16_rn(v.x - __bfloat162float(h0));
        __nv_bfloat16 l1 = __float2bfloat16_rn(v.y - __bfloat162float(h1));
        __nv_bfloat16 l2 = __float2bfloat16_rn(v.z - __bfloat162float(h2));
        __nv_bfloat16 l3 = __float2bfloat16_rn(v.w - __bfloat162float(h3));
        __nv_bfloat162* hp = (__nv_bfloat162*)(hi + 4 * idx4);
        __nv_bfloat162* lp = (__nv_bfloat162*)(lo + 4 * idx4);
        hp[0] = __nv_bfloat162(h0, h1); hp[1] = __nv_bfloat162(h2, h3);
        lp[0] = __nv_bfloat162(l0, l1); lp[1] = __nv_bfloat162(l2, l3);
    }
}

// ============================================================
// Kernel 1: bf16 mma.sync similarity GEMM, 3-stage cp.async pipe
// (exact R8 winner)
// ============================================================
#define TILE_B 16384
#define STAGE_B (4 * TILE_B)
#define NKT 16

__global__ __launch_bounds__(256, 1) void gemm_mma(void) {
    extern __shared__ char smem[];
    const uint32_t sb = smem_u32(smem);
    const int tid = threadIdx.x;
    const int wid = tid >> 5, ln = tid & 31;
    const int bm0 = blockIdx.y * 128;
    const int bn0 = blockIdx.x * 128;
    const int wm = wid & 3;
    const int wn = wid >> 2;

    const int which = tid >> 6;
    const int t64 = tid & 63;
    const __nv_bfloat16* gsrc;
    int row0;
    if      (which == 0) { gsrc = g_ahi; row0 = bm0; }
    else if (which == 1) { gsrc = g_alo; row0 = bm0; }
    else if (which == 2) { gsrc = g_bhi; row0 = bn0; }
    else                 { gsrc = g_blo; row0 = bn0; }
    const char* gbase = (const char*)gsrc + (size_t)row0 * (DD * 2);
    const uint32_t sbase_w = sb + which * TILE_B;

    auto issue = [&](int stage, int kt) {
        const char* gp = gbase + (size_t)kt * 128;
        const uint32_t sp = sbase_w + stage * STAGE_B;
        #pragma unroll
        for (int j = 0; j < 16; j++) {
            int chunk = t64 + 64 * j;
            int row = chunk >> 3, cc = chunk & 7;
            cp16(sp + swz128(row * 128 + cc * 16),
                 gp + (size_t)row * (DD * 2) + cc * 16);
        }
        asm volatile("cp.async.commit_group;" ::: "memory");
    };

    float acc[2][8][4];
    #pragma unroll
    for (int am = 0; am < 2; am++)
        #pragma unroll
        for (int na = 0; na < 8; na++)
            #pragma unroll
            for (int q = 0; q < 4; q++) acc[am][na][q] = 0.f;

    issue(0, 0);
    issue(1, 1);

    const int a_row = (ln & 7) + ((ln >> 3) & 1) * 8;
    const int a_kb  = (ln >> 4) * 16;
    const int b_row = (ln & 7) + (ln >> 4) * 8;
    const int b_kb  = ((ln >> 3) & 1) * 16;

    int stage = 0;
    #pragma unroll 1
    for (int kt = 0; kt < NKT; kt++) {
        if (kt + 2 < NKT) {
            asm volatile("cp.async.wait_group 1;" ::: "memory");
        } else {
            asm volatile("cp.async.wait_group 0;" ::: "memory");
        }
        __syncthreads();
        if (kt + 2 < NKT) {
            int ns = stage + 2; if (ns >= 3) ns -= 3;
            issue(ns, kt + 2);
        }

        const uint32_t st = sb + stage * STAGE_B;
        const uint32_t aHi = st, aLo = st + TILE_B;
        const uint32_t bHi = st + 2 * TILE_B, bLo = st + 3 * TILE_B;

        #pragma unroll
        for (int ks = 0; ks < 4; ks++) {
            const int kb = ks * 32;
            uint32_t ah[2][4], al[2][4], bh[8][2], bl[8][2];
            #pragma unroll
            for (int am = 0; am < 2; am++) {
                uint32_t off = swz128((wm * 32 + am * 16 + a_row) * 128 + kb + a_kb);
                ldsm_x4(ah[am], aHi + off);
                ldsm_x4(al[am], aLo + off);
            }
            #pragma unroll
            for (int p = 0; p < 4; p++) {
                uint32_t off = swz128((wn * 64 + p * 16 + b_row) * 128 + kb + b_kb);
                uint32_t r4[4];
                ldsm_x4(r4, bHi + off);
                bh[2*p][0] = r4[0]; bh[2*p][1] = r4[1];
                bh[2*p+1][0] = r4[2]; bh[2*p+1][1] = r4[3];
                ldsm_x4(r4, bLo + off);
                bl[2*p][0] = r4[0]; bl[2*p][1] = r4[1];
                bl[2*p+1][0] = r4[2]; bl[2*p+1][1] = r4[3];
            }
            #pragma unroll
            for (int am = 0; am < 2; am++)
                #pragma unroll
                for (int na = 0; na < 8; na++) {
                    mma16816(acc[am][na], ah[am], bh[na]);
                    mma16816(acc[am][na], ah[am], bl[na]);
                    mma16816(acc[am][na], al[am], bh[na]);
                }
        }
        __syncthreads();
        stage++; if (stage >= 3) stage = 0;
    }

    const int rq = ln >> 2, cq = (ln & 3) * 2;
    #pragma unroll
    for (int am = 0; am < 2; am++) {
        const int m0 = bm0 + wm * 32 + am * 16 + rq;
        const int m1 = m0 + 8;
        const int i0 = m0 / 36, r0 = m0 - i0 * 36;
        const int i1 = m1 / 36, r1 = m1 - i1 * 36;
        #pragma unroll
        for (int na = 0; na < 8; na++) {
            const int n = bn0 + wn * 64 + na * 8 + cq;
            const int cidx = n >> 5, w = n & 31;
            float* p0 = g_sim + ((size_t)cidx * NI + i0) * (RR * WW) + r0 * WW + w;
            float* p1 = g_sim + ((size_t)cidx * NI + i1) * (RR * WW) + r1 * WW + w;
            float2 v0 = {acc[am][na][0], acc[am][na][1]};
            float2 v1 = {acc[am][na][2], acc[am][na][3]};
            *(float2*)p0 = v0;
            *(float2*)p1 = v1;
        }
    }
}

// ============================================================
// Kernel 4: per-(image,caption) focal attention + cosine
// Phases 1+2a: thread-per-query (no shuffles).
// Phase 2b: warp-per-4-queries (R8 winner form).
// ============================================================
__global__ __launch_bounds__(256, 8) void pair_kernel(float* __restrict__ out) {
    const int i = blockIdx.x, c = blockIdx.y;
    __shared__ float M[36 * 33];
    __shared__ float Gi[36 * 37];
    __shared__ float Gc[32 * 33];
    __shared__ __align__(16) float AtP[36 * 36];   // [r][w] row stride 36
    __shared__ __align__(16) float AiP[32 * 36];   // [ww][r] row stride 36
    __shared__ float rinv[36], cinv[32];
    __shared__ float numT[32], numI[36];
    __shared__ float accT, accI;

    const int tid = threadIdx.x;
    if (tid == 0) { accT = 0.f; accI = 0.f; }

    const float* simp = g_sim + ((size_t)c * NI + i) * (RR * WW);
    for (int g = tid; g < RR * WW; g += 256) {
        int r = g >> 5, w = g & 31;
        M[r * 33 + w] = simp[g];
    }
    const float* gip = g_gimg + (size_t)i * (RR * RR);
    for (int g = tid; g < RR * RR; g += 256) {
        int r = g / 36, rr = g % 36;
        Gi[r * 37 + rr] = gip[g];
    }
    const float* gcp = g_gcap + (size_t)c * (WW * WW);
    for (int g = tid; g < WW * WW; g += 256) {
        int w = g >> 5, ww = g & 31;
        Gc[w * 33 + ww] = gcp[g];
    }
    __syncthreads();

    // ---- phase 1: inverse norms, thread-per-reduction ----
    if (tid < 36) {
        const float* Mr = &M[tid * 33];
        float s = 0.f;
        #pragma unroll 8
        for (int w = 0; w < 32; w++) {
            float v = Mr[w];
            v = v > 0.f ? v : 0.1f * v;
            s = fmaf(v, v, s);
        }
        rinv[tid] = __fdividef(1.f, __fsqrt_rn(s) + 1e-8f);
    } else if (tid < 68) {
        const int w = tid - 36;
        float s = 0.f;
        #pragma unroll 6
        for (int r = 0; r < 36; r++) {
            float v = M[r * 33 + w];
            v = v > 0.f ? v : 0.1f * v;
            s = fmaf(v, v, s);
        }
        cinv[w] = __fdividef(1.f, __fsqrt_rn(s) + 1e-8f);
    }
    __syncthreads();

    // ---- phase 2a: softmax + focal mask + numerator, thread-per-query ----
    if (tid < 32) {
        // t2i query w = tid: softmax over 36 regions
        const int w = tid;
        float s = 0.f;
        #pragma unroll 6
        for (int r = 0; r < 36; r++) {
            float m = M[r * 33 + w];
            float l = (m > 0.f ? m : 0.1f * m) * rinv[r];
            float e = __expf(20.f * l);
            AtP[r * 36 + w] = e;
            s += e;
        }
        float te = 0.f, nm = 0.f;
        #pragma unroll 6
        for (int r = 0; r < 36; r++) {
            float e = AtP[r * 36 + w];
            if (36.f * e > s) {
                te += e;
                nm = fmaf(e, M[r * 33 + w], nm);
            }
        }
        float it = __fdividef(1.f, te);
        #pragma unroll 6
        for (int r = 0; r < 36; r++) {
            float e = AtP[r * 36 + w];
            AtP[r * 36 + w] = (36.f * e > s) ? e * it : 0.f;
        }
        numT[w] = nm * it;
    } else if (tid < 68) {
        // i2t query r = tid-32: softmax over 32 words
        const int r = tid - 32;
        float s = 0.f;
        #pragma unroll 8
        for (int ww = 0; ww < 32; ww++) {
            float m = M[r * 33 + ww];
            float l = (m > 0.f ? m : 0.1f * m) * cinv[ww];
            float e = __expf(20.f * l);
            AiP[ww * 36 + r] = e;
            s += e;
        }
        float te = 0.f, nm = 0.f;
        #pragma unroll 8
        for (int ww = 0; ww < 32; ww++) {
            float e = AiP[ww * 36 + r];
            if (32.f * e > s) {
                te += e;
                nm = fmaf(e, M[r * 33 + ww], nm);
            }
        }
        float it = __fdividef(1.f, te);
        #pragma unroll 8
        for (int ww = 0; ww < 32; ww++) {
            float e = AiP[ww * 36 + r];
            AiP[ww * 36 + r] = (32.f * e > s) ? e * it : 0.f;
        }
        numI[r] = nm * it;
    }
    __syncthreads();

    const int wd = tid >> 5, ln = tid & 31;

    // ---- phase 2b: batched quadratic forms, 4 queries per sweep ----
    float tAcc = 0.f, iAcc = 0.f;
    for (int t = wd; t < 17; t += 8) {
        if (t < 8) {
            const int w0 = t * 4;
            const bool h2 = ln < 4;
            float4 in1 = {0.f, 0.f, 0.f, 0.f};
            float4 in2 = {0.f, 0.f, 0.f, 0.f};
            const float* giR  = &Gi[ln * 37];
            const float* giR2 = &Gi[(ln + 32) * 37];
            #pragma unroll 6
            for (int rr = 0; rr < 36; rr++) {
                float gv = giR[rr];
                float4 a4 = *(const float4*)&AtP[rr * 36 + w0];
                in1.x = fmaf(gv, a4.x, in1.x);
                in1.y = fmaf(gv, a4.y, in1.y);
                in1.z = fmaf(gv, a4.z, in1.z);
                in1.w = fmaf(gv, a4.w, in1.w);
                if (h2) {
                    float gv2 = giR2[rr];
                    in2.x = fmaf(gv2, a4.x, in2.x);
                    in2.y = fmaf(gv2, a4.y, in2.y);
                    in2.z = fmaf(gv2, a4.z, in2.z);
                    in2.w = fmaf(gv2, a4.w, in2.w);
                }
            }
            float4 at1 = *(const float4*)&AtP[ln * 36 + w0];
            float4 at2 = {0.f, 0.f, 0.f, 0.f};
            if (h2) at2 = *(const float4*)&AtP[(ln + 32) * 36 + w0];
            float4 d;
            d.x = at1.x * in1.x + at2.x * in2.x;
            d.y = at1.y * in1.y + at2.y * in2.y;
            d.z = at1.z * in1.z + at2.z * in2.z;
            d.w = at1.w * in1.w + at2.w * in2.w;
            wsum4(d);
            #pragma unroll
            for (int q = 0; q < 4; q++) {
                float d2 = fmaxf((&d.x)[q], 1e-16f);
                float gd = fmaxf(Gc[(w0 + q) * 33 + (w0 + q)], 1e-16f);
                tAcc += numT[w0 + q] * __frsqrt_rn(d2) * __frsqrt_rn(gd);
            }
        } else {
            const int r0 = (t - 8) * 4;
            float4 in = {0.f, 0.f, 0.f, 0.f};
            const float* gcR = &Gc[ln * 33];
            #pragma unroll 8
            for (int ww = 0; ww < 32; ww++) {
                float gv = gcR[ww];
                float4 a4 = *(const float4*)&AiP[ww * 36 + r0];
                in.x = fmaf(gv, a4.x, in.x);
                in.y = fmaf(gv, a4.y, in.y);
                in.z = fmaf(gv, a4.z, in.z);
                in.w = fmaf(gv, a4.w, in.w);
            }
            float4 at = *(const float4*)&AiP[ln * 36 + r0];
            float4 d;
            d.x = at.x * in.x;
            d.y = at.y * in.y;
            d.z = at.z * in.z;
            d.w = at.w * in.w;
            wsum4(d);
            #pragma unroll
            for (int q = 0; q < 4; q++) {
                float d2 = fmaxf((&d.x)[q], 1e-16f);
                float gd = fmaxf(Gi[(r0 + q) * 37 + (r0 + q)], 1e-16f);
                iAcc += numI[r0 + q] * __frsqrt_rn(d2) * __frsqrt_rn(gd);
            }
        }
    }
    if (ln == 0) {
        atomicAdd(&accT, tAcc);
        atomicAdd(&accI, iAcc);
    }
    __syncthreads();
    if (tid == 0) out[(size_t)i * NC + c] = accT * (1.f / 32.f) + accI * (1.f / 36.f);
}

// ============================================================
extern "C" void kernel_launch(void* const* d_in, const int* in_sizes, int n_in,
                              void* d_out, int out_size) {
    const float* images   = (const float*)d_in[0];
    const float* captions = (const float*)d_in[1];
    float* out = (float*)d_out;

    const int SMEM_TOTAL = 3 * STAGE_B;   // 192 KB
    cudaFuncSetAttribute(gemm_mma, cudaFuncAttributeMaxDynamicSharedMemorySize, SMEM_TOTAL);

    const size_t n4 = ((size_t)MROWS * DD + (size_t)NCOLS * DD) / 4;
    const unsigned conv_blocks = (unsigned)((n4 + 255) / 256);   // 8704
    prep_kernel<<<conv_blocks + 256, 256>>>(images, captions);   // gram first, convert after
    gemm_mma<<<dim3(32, 36), 256, SMEM_TOTAL>>>();
    pair_kernel<<<dim3(128, 128), 256>>>(out);
}